// round 1
// baseline (speedup 1.0000x reference)
#include <cuda_runtime.h>
#include <cuda_bf16.h>

#define N_NODES 50000
#define N_EDGES 500000
#define HID 128
#define OUTD 64

// ---------------- scratch (device globals; no runtime allocation) ----------
__device__ float g_agg[N_NODES * HID];
__device__ float g_h1[N_NODES * HID];
__device__ float g_h2[N_NODES * HID];
__device__ int   g_deg[N_NODES];
__device__ int   g_start[N_NODES];
__device__ int   g_cursor[N_NODES];
__device__ int   g_csr[N_EDGES];
__device__ int   g_bsum[64];

// ---------------- packed f32x2 helpers -------------------------------------
__device__ __forceinline__ unsigned long long pk2(float a) {
    unsigned long long r;
    asm("mov.b64 %0, {%1, %1};" : "=l"(r) : "f"(a));
    return r;
}
__device__ __forceinline__ unsigned long long ffma2(unsigned long long a,
                                                    unsigned long long b,
                                                    unsigned long long c) {
    unsigned long long d;
    asm("fma.rn.f32x2 %0, %1, %2, %3;" : "=l"(d) : "l"(a), "l"(b), "l"(c));
    return d;
}
__device__ __forceinline__ float2 unpk2(unsigned long long v) {
    float2 f;
    asm("mov.b64 {%0, %1}, %2;" : "=f"(f.x), "=f"(f.y) : "l"(v));
    return f;
}

// ---------------- CSR build -------------------------------------------------
__global__ void k_zero_deg() {
    int i = blockIdx.x * blockDim.x + threadIdx.x;
    if (i < N_NODES) g_deg[i] = 0;
}

__global__ void k_count(const int* __restrict__ ei) {
    int e = blockIdx.x * blockDim.x + threadIdx.x;
    if (e < N_EDGES) atomicAdd(&g_deg[ei[N_EDGES + e]], 1);
}

__global__ void k_scan1() {
    __shared__ int sh[1024];
    int tid = threadIdx.x;
    int i = blockIdx.x * 1024 + tid;
    int v = (i < N_NODES) ? g_deg[i] : 0;
    sh[tid] = v;
    __syncthreads();
    for (int off = 1; off < 1024; off <<= 1) {
        int t = (tid >= off) ? sh[tid - off] : 0;
        __syncthreads();
        sh[tid] += t;
        __syncthreads();
    }
    if (i < N_NODES) g_start[i] = sh[tid] - v;   // exclusive
    if (tid == 1023) g_bsum[blockIdx.x] = sh[1023];
}

__global__ void k_scan2(int nb) {
    if (threadIdx.x == 0 && blockIdx.x == 0) {
        int acc = 0;
        for (int i = 0; i < nb; i++) {
            int v = g_bsum[i];
            g_bsum[i] = acc;
            acc += v;
        }
    }
}

__global__ void k_scan3() {
    int i = blockIdx.x * blockDim.x + threadIdx.x;
    if (i < N_NODES) {
        int s = g_start[i] + g_bsum[i >> 10];
        g_start[i] = s;
        g_cursor[i] = s;
    }
}

__global__ void k_fill(const int* __restrict__ ei) {
    int e = blockIdx.x * blockDim.x + threadIdx.x;
    if (e < N_EDGES) {
        int dst = ei[N_EDGES + e];
        int p = atomicAdd(&g_cursor[dst], 1);
        g_csr[p] = ei[e];
    }
}

// ---------------- mean aggregation (pull, one warp per node) ----------------
__global__ void k_aggregate(const float* __restrict__ hin) {
    int gw = (blockIdx.x * blockDim.x + threadIdx.x) >> 5;
    int lane = threadIdx.x & 31;
    if (gw >= N_NODES) return;

    int s = g_start[gw];
    int d = g_deg[gw];
    const float* base = hin + lane * 4;

    float4 acc = make_float4(0.f, 0.f, 0.f, 0.f);
    int j = 0;
    for (; j + 4 <= d; j += 4) {
        int s0 = g_csr[s + j + 0];
        int s1 = g_csr[s + j + 1];
        int s2 = g_csr[s + j + 2];
        int s3 = g_csr[s + j + 3];
        float4 v0 = *(const float4*)(base + s0 * HID);
        float4 v1 = *(const float4*)(base + s1 * HID);
        float4 v2 = *(const float4*)(base + s2 * HID);
        float4 v3 = *(const float4*)(base + s3 * HID);
        acc.x += v0.x + v1.x + v2.x + v3.x;
        acc.y += v0.y + v1.y + v2.y + v3.y;
        acc.z += v0.z + v1.z + v2.z + v3.z;
        acc.w += v0.w + v1.w + v2.w + v3.w;
    }
    for (; j < d; j++) {
        int s0 = g_csr[s + j];
        float4 v0 = *(const float4*)(base + s0 * HID);
        acc.x += v0.x; acc.y += v0.y; acc.z += v0.z; acc.w += v0.w;
    }
    float inv = (d > 0) ? (1.0f / (float)d) : 0.0f;
    float4 o;
    o.x = acc.x * inv; o.y = acc.y * inv; o.z = acc.z * inv; o.w = acc.w * inv;
    *(float4*)(g_agg + gw * HID + lane * 4) = o;
}

// ---------------- fused dual GEMM: out = A1@W1 + A2@W2 + b (+relu) ---------
// A1, A2: [N, 128] row-major.  W1, W2: [128, BN] row-major.  out: [N, BN].
// BM=128 rows per block, BK=16, 256 threads.
// Thread grid: TX col-groups (8 cols each) x TY row-groups (RPT rows each).
template <int BN, int TX, int RPT, bool RELU>
__global__ __launch_bounds__(256, 1)
void gemm_fused(const float* __restrict__ A1, const float* __restrict__ A2,
                const float* __restrict__ W1, const float* __restrict__ W2,
                const float* __restrict__ bias, float* __restrict__ out) {
    constexpr int TY = 256 / TX;
    constexpr int BM = 128;
    constexpr int BK = 16;
    constexpr int AS = BK + 2;    // 18: float2-aligned, bank-safe row stride
    constexpr int WS = BN + 4;    // 132 / 68: float4-aligned row stride
    static_assert(TY * RPT == BM, "tile mismatch");

    __shared__ __align__(16) float sA1[BM * AS];
    __shared__ __align__(16) float sA2[BM * AS];
    __shared__ __align__(16) float sW1[BK * WS];
    __shared__ __align__(16) float sW2[BK * WS];

    const int tid = threadIdx.x;
    const int tx = tid % TX;
    const int ty = tid / TX;
    const int row0 = blockIdx.x * BM;
    const int c0 = tx * 8;

    unsigned long long acc[RPT][4];
#pragma unroll
    for (int i = 0; i < RPT; i++)
#pragma unroll
        for (int j = 0; j < 4; j++) acc[i][j] = 0ull;

    for (int k0 = 0; k0 < HID; k0 += BK) {
        // ---- stage A tiles (BM x BK each): 512 float4 per matrix, 2/thread
#pragma unroll
        for (int l = 0; l < 2; l++) {
            int idx = tid + l * 256;          // 0..511
            int r = idx >> 2;                 // 0..127
            int kg = (idx & 3) * 4;           // 0,4,8,12
            int rg = row0 + r;
            if (rg > N_NODES - 1) rg = N_NODES - 1;
            float4 v1 = *(const float4*)(A1 + rg * HID + k0 + kg);
            float4 v2 = *(const float4*)(A2 + rg * HID + k0 + kg);
            float* p1 = &sA1[r * AS + kg];
            float* p2 = &sA2[r * AS + kg];
            p1[0] = v1.x; p1[1] = v1.y; p1[2] = v1.z; p1[3] = v1.w;
            p2[0] = v2.x; p2[1] = v2.y; p2[2] = v2.z; p2[3] = v2.w;
        }
        // ---- stage W tiles (BK x BN each)
        constexpr int WF4 = BK * BN / 4;      // 512 (BN=128) or 256 (BN=64)
#pragma unroll
        for (int l = 0; l < (WF4 + 255) / 256; l++) {
            int idx = tid + l * 256;
            if ((WF4 % 256 == 0) || idx < WF4) {
                int kk = idx / (BN / 4);
                int cg = (idx % (BN / 4)) * 4;
                *(float4*)&sW1[kk * WS + cg] = *(const float4*)(W1 + (k0 + kk) * BN + cg);
                *(float4*)&sW2[kk * WS + cg] = *(const float4*)(W2 + (k0 + kk) * BN + cg);
            }
        }
        __syncthreads();

#pragma unroll
        for (int kk = 0; kk < BK; kk += 2) {
            float2 a1[RPT], a2[RPT];
#pragma unroll
            for (int i = 0; i < RPT; i++) {
                int r = ty * RPT + i;
                a1[i] = *(const float2*)&sA1[r * AS + kk];
                a2[i] = *(const float2*)&sA2[r * AS + kk];
            }
#pragma unroll
            for (int kh = 0; kh < 2; kh++) {
                const int krow = (kk + kh) * WS + c0;
                ulonglong2 wa1 = *(const ulonglong2*)&sW1[krow];
                ulonglong2 wb1 = *(const ulonglong2*)&sW1[krow + 4];
                ulonglong2 wa2 = *(const ulonglong2*)&sW2[krow];
                ulonglong2 wb2 = *(const ulonglong2*)&sW2[krow + 4];
                unsigned long long w1p[4] = {wa1.x, wa1.y, wb1.x, wb1.y};
                unsigned long long w2p[4] = {wa2.x, wa2.y, wb2.x, wb2.y};
#pragma unroll
                for (int i = 0; i < RPT; i++) {
                    unsigned long long pa1 = pk2(kh ? a1[i].y : a1[i].x);
                    unsigned long long pa2 = pk2(kh ? a2[i].y : a2[i].x);
#pragma unroll
                    for (int j = 0; j < 4; j++) {
                        acc[i][j] = ffma2(pa1, w1p[j], acc[i][j]);
                        acc[i][j] = ffma2(pa2, w2p[j], acc[i][j]);
                    }
                }
            }
        }
        __syncthreads();
    }

    // ---- epilogue: bias (+relu), store
#pragma unroll
    for (int i = 0; i < RPT; i++) {
        int r = row0 + ty * RPT + i;
        if (r < N_NODES) {
#pragma unroll
            for (int j = 0; j < 4; j++) {
                float2 v = unpk2(acc[i][j]);
                int c = c0 + j * 2;
                v.x += bias[c];
                v.y += bias[c + 1];
                if (RELU) {
                    v.x = fmaxf(v.x, 0.f);
                    v.y = fmaxf(v.y, 0.f);
                }
                *(float2*)(out + r * BN + c) = v;
            }
        }
    }
}

// ---------------- launch ----------------------------------------------------
extern "C" void kernel_launch(void* const* d_in, const int* in_sizes, int n_in,
                              void* d_out, int out_size) {
    const float* x   = (const float*)d_in[0];
    const int*   ei  = (const int*)d_in[1];
    const float* W1l = (const float*)d_in[2];
    const float* W1r = (const float*)d_in[3];
    const float* b1  = (const float*)d_in[4];
    const float* W2l = (const float*)d_in[5];
    const float* W2r = (const float*)d_in[6];
    const float* b2  = (const float*)d_in[7];
    const float* W3l = (const float*)d_in[8];
    const float* W3r = (const float*)d_in[9];
    const float* b3  = (const float*)d_in[10];
    float* out = (float*)d_out;

    float *agg, *h1, *h2;
    cudaGetSymbolAddress((void**)&agg, g_agg);
    cudaGetSymbolAddress((void**)&h1, g_h1);
    cudaGetSymbolAddress((void**)&h2, g_h2);

    const int NB_N = (N_NODES + 255) / 256;       // 196
    const int NB_E = (N_EDGES + 255) / 256;       // 1954
    const int NB_S = (N_NODES + 1023) / 1024;     // 49
    const int NB_AGG = (N_NODES + 7) / 8;         // 6250 (8 warps/block)
    const int NB_GEMM = (N_NODES + 127) / 128;    // 391

    // CSR build (per launch; deterministic inputs -> same CSR contents)
    k_zero_deg<<<NB_N, 256>>>();
    k_count<<<NB_E, 256>>>(ei);
    k_scan1<<<NB_S, 1024>>>();
    k_scan2<<<1, 32>>>(NB_S);
    k_scan3<<<NB_N, 256>>>();
    k_fill<<<NB_E, 256>>>(ei);

    // Layer 1
    k_aggregate<<<NB_AGG, 256>>>(x);
    gemm_fused<128, 16, 8, true><<<NB_GEMM, 256>>>(agg, x, W1l, W1r, b1, h1);
    // Layer 2
    k_aggregate<<<NB_AGG, 256>>>(h1);
    gemm_fused<128, 16, 8, true><<<NB_GEMM, 256>>>(agg, h1, W2l, W2r, b2, h2);
    // Layer 3
    k_aggregate<<<NB_AGG, 256>>>(h2);
    gemm_fused<64, 8, 4, false><<<NB_GEMM, 256>>>(agg, h2, W3l, W3r, b3, out);
}

// round 6
// speedup vs baseline: 1.6632x; 1.6632x over previous
#include <cuda_runtime.h>
#include <cuda_bf16.h>
#include <cstdint>

#define N_NODES 50000
#define N_EDGES 500000
#define HID 128
#define OUTD 64

// ---------------- scratch (device globals; no runtime allocation) ----------
__device__ float g_agg[N_NODES * HID];
__device__ float g_h1[N_NODES * HID];
__device__ float g_h2[N_NODES * HID];
__device__ int   g_deg[N_NODES];
__device__ int   g_start[N_NODES];
__device__ int   g_cursor[N_NODES];
__device__ int   g_csr[N_EDGES];
__device__ int   g_bsum[64];

// ---------------- CSR build -------------------------------------------------
__global__ void k_zero_deg() {
    int i = blockIdx.x * blockDim.x + threadIdx.x;
    if (i < N_NODES) g_deg[i] = 0;
}

__global__ void k_count(const int* __restrict__ ei) {
    int e = blockIdx.x * blockDim.x + threadIdx.x;
    if (e < N_EDGES) atomicAdd(&g_deg[ei[N_EDGES + e]], 1);
}

__global__ void k_scan1() {
    __shared__ int sh[1024];
    int tid = threadIdx.x;
    int i = blockIdx.x * 1024 + tid;
    int v = (i < N_NODES) ? g_deg[i] : 0;
    sh[tid] = v;
    __syncthreads();
    for (int off = 1; off < 1024; off <<= 1) {
        int t = (tid >= off) ? sh[tid - off] : 0;
        __syncthreads();
        sh[tid] += t;
        __syncthreads();
    }
    if (i < N_NODES) g_start[i] = sh[tid] - v;   // exclusive
    if (tid == 1023) g_bsum[blockIdx.x] = sh[1023];
}

__global__ void k_scan2(int nb) {
    __shared__ int sh[64];
    int t = threadIdx.x;
    int v = (t < nb) ? g_bsum[t] : 0;
    sh[t] = v;
    __syncthreads();
    for (int off = 1; off < 64; off <<= 1) {
        int u = (t >= off) ? sh[t - off] : 0;
        __syncthreads();
        sh[t] += u;
        __syncthreads();
    }
    if (t < nb) g_bsum[t] = sh[t] - v;           // exclusive
}

__global__ void k_scan3() {
    int i = blockIdx.x * blockDim.x + threadIdx.x;
    if (i < N_NODES) {
        int s = g_start[i] + g_bsum[i >> 10];
        g_start[i] = s;
        g_cursor[i] = s;
    }
}

__global__ void k_fill(const int* __restrict__ ei) {
    int e = blockIdx.x * blockDim.x + threadIdx.x;
    if (e < N_EDGES) {
        int dst = ei[N_EDGES + e];
        int p = atomicAdd(&g_cursor[dst], 1);
        g_csr[p] = ei[e];
    }
}

// ---------------- mean aggregation (pull, one warp per node, 128-wide) ------
__global__ void k_aggregate(const float* __restrict__ hin) {
    int gw = (blockIdx.x * blockDim.x + threadIdx.x) >> 5;
    int lane = threadIdx.x & 31;
    if (gw >= N_NODES) return;

    int s = g_start[gw];
    int d = g_deg[gw];
    const float* base = hin + lane * 4;

    float4 acc = make_float4(0.f, 0.f, 0.f, 0.f);
    int j = 0;
    for (; j + 4 <= d; j += 4) {
        int s0 = g_csr[s + j + 0];
        int s1 = g_csr[s + j + 1];
        int s2 = g_csr[s + j + 2];
        int s3 = g_csr[s + j + 3];
        float4 v0 = *(const float4*)(base + s0 * HID);
        float4 v1 = *(const float4*)(base + s1 * HID);
        float4 v2 = *(const float4*)(base + s2 * HID);
        float4 v3 = *(const float4*)(base + s3 * HID);
        acc.x += v0.x + v1.x + v2.x + v3.x;
        acc.y += v0.y + v1.y + v2.y + v3.y;
        acc.z += v0.z + v1.z + v2.z + v3.z;
        acc.w += v0.w + v1.w + v2.w + v3.w;
    }
    for (; j < d; j++) {
        int s0 = g_csr[s + j];
        float4 v0 = *(const float4*)(base + s0 * HID);
        acc.x += v0.x; acc.y += v0.y; acc.z += v0.z; acc.w += v0.w;
    }
    float inv = (d > 0) ? (1.0f / (float)d) : 0.0f;
    float4 o;
    o.x = acc.x * inv; o.y = acc.y * inv; o.z = acc.z * inv; o.w = acc.w * inv;
    *(float4*)(g_agg + gw * HID + lane * 4) = o;
}

// ---- layer-3 epilogue: out_i = mean_j P_j + R_i (PR = [P|R], 128 wide) -----
__global__ void k_agg_add(const float* __restrict__ PR, float* __restrict__ out) {
    int gw = (blockIdx.x * blockDim.x + threadIdx.x) >> 5;
    int lane = threadIdx.x & 31;
    if (gw >= N_NODES) return;

    int s = g_start[gw];
    int d = g_deg[gw];
    const float* base = PR + lane * 2;

    float2 acc = make_float2(0.f, 0.f);
    int j = 0;
    for (; j + 4 <= d; j += 4) {
        int s0 = g_csr[s + j + 0];
        int s1 = g_csr[s + j + 1];
        int s2 = g_csr[s + j + 2];
        int s3 = g_csr[s + j + 3];
        float2 v0 = *(const float2*)(base + s0 * HID);
        float2 v1 = *(const float2*)(base + s1 * HID);
        float2 v2 = *(const float2*)(base + s2 * HID);
        float2 v3 = *(const float2*)(base + s3 * HID);
        acc.x += v0.x + v1.x + v2.x + v3.x;
        acc.y += v0.y + v1.y + v2.y + v3.y;
    }
    for (; j < d; j++) {
        int s0 = g_csr[s + j];
        float2 v0 = *(const float2*)(base + s0 * HID);
        acc.x += v0.x; acc.y += v0.y;
    }
    float inv = (d > 0) ? (1.0f / (float)d) : 0.0f;
    float2 r = *(const float2*)(PR + gw * HID + 64 + lane * 2);
    float2 o;
    o.x = acc.x * inv + r.x;
    o.y = acc.y * inv + r.y;
    *(float2*)(out + gw * OUTD + lane * 2) = o;
}

// ---------------- tf32 mma.sync GEMM ----------------------------------------
// D[128 rows, 128 cols] = Acat[128, K] @ Wcat[K, 128]  (+bias, +relu)
// MODE 0: K=256, Acat=[A1|A2], Wcat=[W1;W2] (each 128x128). out += bias, relu.
// MODE 1: K=128, Acat=A1, Wcat=[W3l|W3r] (each 128x64).
//         out[:,c] += (c>=64 ? bias[c-64] : 0), no relu.
// 256 threads = 8 warps; warp (w) owns rows [ (w>>1)*32, +32 ), cols [ (w&1)*64, +64 ).
// Fragment-order SMEM staging: every mma operand load is a conflict-free LDS.128.
__device__ __forceinline__ uint32_t f2tf32(float v) {
    uint32_t t;
    asm("cvt.rn.tf32.f32 %0, %1;" : "=r"(t) : "f"(v));
    return t;
}

__device__ __forceinline__ void mma_tf32(float* c, const uint32_t* a,
                                         uint32_t b0, uint32_t b1) {
    asm volatile(
        "mma.sync.aligned.m16n8k8.row.col.f32.tf32.tf32.f32 "
        "{%0,%1,%2,%3}, {%4,%5,%6,%7}, {%8,%9}, {%0,%1,%2,%3};"
        : "+f"(c[0]), "+f"(c[1]), "+f"(c[2]), "+f"(c[3])
        : "r"(a[0]), "r"(a[1]), "r"(a[2]), "r"(a[3]), "r"(b0), "r"(b1));
}

template <int MODE>
__global__ __launch_bounds__(256)
void gemm_mma(const float* __restrict__ A1, const float* __restrict__ A2,
              const float* __restrict__ W1, const float* __restrict__ W2,
              const float* __restrict__ bias, float* __restrict__ out) {
    // fragment-order tiles: 4096 f32 each (16 KB + 16 KB)
    __shared__ uint32_t sA[4096];
    __shared__ uint32_t sB[4096];

    const int tid = threadIdx.x;
    const int warp = tid >> 5;
    const int lane = tid & 31;
    const int rs4 = warp >> 1;        // row stripe 0..3 (32 rows)
    const int cs2 = warp & 1;         // col stripe 0..1 (64 cols)
    const int row0 = blockIdx.x * 128;

    float acc[2][8][4];
#pragma unroll
    for (int m = 0; m < 2; m++)
#pragma unroll
        for (int t = 0; t < 8; t++)
#pragma unroll
            for (int q = 0; q < 4; q++) acc[m][t][q] = 0.f;

    const int KB = (MODE == 0) ? 8 : 4;   // k-blocks of 32
    for (int kb = 0; kb < KB; kb++) {
        // ---- stage A tile [128 rows x 32 k] into fragment order ----
        const float* Asrc = (MODE == 0 && kb >= 4) ? A2 : A1;
        const int kbase = (MODE == 0) ? ((kb & 3) * 32) : (kb * 32);
#pragma unroll
        for (int l = 0; l < 16; l++) {
            int idx = tid + l * 256;          // 0..4095
            int r = idx >> 5;
            int kl = idx & 31;
            int rg = row0 + r;
            if (rg >= N_NODES) rg = N_NODES - 1;
            uint32_t tv = f2tf32(Asrc[(size_t)rg * HID + kbase + kl]);
            int ks = kl >> 3, kk = kl & 7;
            int rr = r & 31, rsd = r >> 5;
            int m = rr >> 4, r16 = rr & 15;
            int w = m * 4 + (kk >> 2) * 2 + (r16 >> 3);
            int ln = (r16 & 7) * 4 + (kk & 3);
            sA[(((ks * 4 + rsd) * 2 + (w >> 2)) * 32 + ln) * 4 + (w & 3)] = tv;
        }
        // ---- stage B tile [32 k x 128 n] into fragment order ----
#pragma unroll
        for (int l = 0; l < 16; l++) {
            int idx = tid + l * 256;
            int n = idx & 127;
            int kl = idx >> 7;                // 0..31
            float v;
            if (MODE == 0) {
                const float* Ws = (kb < 4) ? W1 : W2;
                v = Ws[((kb & 3) * 32 + kl) * 128 + n];
            } else {
                int kg = kb * 32 + kl;
                v = (n < 64) ? W1[kg * 64 + n] : W2[kg * 64 + (n - 64)];
            }
            uint32_t tv = f2tf32(v);
            int ks = kl >> 3, kk = kl & 7;
            int c2 = n >> 6, nn = n & 63;
            int w = (nn >> 3) * 2 + (kk >> 2);
            int ln = (nn & 7) * 4 + (kk & 3);
            sB[(((ks * 2 + c2) * 4 + (w >> 2)) * 32 + ln) * 4 + (w & 3)] = tv;
        }
        __syncthreads();

        // ---- compute: 4 k-steps of m16n8k8 ----
#pragma unroll
        for (int ks = 0; ks < 4; ks++) {
            uint32_t a[8];
            uint32_t b[16];
            const uint4* pa = (const uint4*)sA;
            const uint4* pb = (const uint4*)sB;
            uint4 a0 = pa[((ks * 4 + rs4) * 2 + 0) * 32 + lane];
            uint4 a1 = pa[((ks * 4 + rs4) * 2 + 1) * 32 + lane];
            a[0] = a0.x; a[1] = a0.y; a[2] = a0.z; a[3] = a0.w;
            a[4] = a1.x; a[5] = a1.y; a[6] = a1.z; a[7] = a1.w;
#pragma unroll
            for (int h = 0; h < 4; h++) {
                uint4 bv = pb[((ks * 2 + cs2) * 4 + h) * 32 + lane];
                b[h * 4 + 0] = bv.x; b[h * 4 + 1] = bv.y;
                b[h * 4 + 2] = bv.z; b[h * 4 + 3] = bv.w;
            }
#pragma unroll
            for (int m = 0; m < 2; m++)
#pragma unroll
                for (int t = 0; t < 8; t++)
                    mma_tf32(acc[m][t], a + m * 4, b[2 * t], b[2 * t + 1]);
        }
        __syncthreads();
    }

    // ---- epilogue: bias (+relu), float2 stores ----
#pragma unroll
    for (int m = 0; m < 2; m++) {
#pragma unroll
        for (int q2 = 0; q2 < 2; q2++) {      // q2=0 -> c0,c1 ; q2=1 -> c2,c3
            int row = row0 + rs4 * 32 + m * 16 + q2 * 8 + (lane >> 2);
            if (row < N_NODES) {
#pragma unroll
                for (int t = 0; t < 8; t++) {
                    int col = cs2 * 64 + t * 8 + (lane & 3) * 2;
                    float2 v;
                    v.x = acc[m][t][q2 * 2 + 0];
                    v.y = acc[m][t][q2 * 2 + 1];
                    if (MODE == 0) {
                        v.x += bias[col];
                        v.y += bias[col + 1];
                        v.x = fmaxf(v.x, 0.f);
                        v.y = fmaxf(v.y, 0.f);
                    } else {
                        if (col >= 64) {
                            v.x += bias[col - 64];
                            v.y += bias[col - 63];
                        }
                    }
                    *(float2*)(out + (size_t)row * 128 + col) = v;
                }
            }
        }
    }
}

// ---------------- launch ----------------------------------------------------
extern "C" void kernel_launch(void* const* d_in, const int* in_sizes, int n_in,
                              void* d_out, int out_size) {
    const float* x   = (const float*)d_in[0];
    const int*   ei  = (const int*)d_in[1];
    const float* W1l = (const float*)d_in[2];
    const float* W1r = (const float*)d_in[3];
    const float* b1  = (const float*)d_in[4];
    const float* W2l = (const float*)d_in[5];
    const float* W2r = (const float*)d_in[6];
    const float* b2  = (const float*)d_in[7];
    const float* W3l = (const float*)d_in[8];
    const float* W3r = (const float*)d_in[9];
    const float* b3  = (const float*)d_in[10];
    float* out = (float*)d_out;

    float *agg, *h1, *h2;
    cudaGetSymbolAddress((void**)&agg, g_agg);
    cudaGetSymbolAddress((void**)&h1, g_h1);
    cudaGetSymbolAddress((void**)&h2, g_h2);

    const int NB_N = (N_NODES + 255) / 256;
    const int NB_E = (N_EDGES + 255) / 256;
    const int NB_S = (N_NODES + 1023) / 1024;     // 49
    const int NB_AGG = (N_NODES + 7) / 8;
    const int NB_GEMM = (N_NODES + 127) / 128;    // 391

    // CSR build
    k_zero_deg<<<NB_N, 256>>>();
    k_count<<<NB_E, 256>>>(ei);
    k_scan1<<<NB_S, 1024>>>();
    k_scan2<<<1, 64>>>(NB_S);
    k_scan3<<<NB_N, 256>>>();
    k_fill<<<NB_E, 256>>>(ei);

    // Layer 1: h1 = relu(agg(x)@W1l + x@W1r + b1)
    k_aggregate<<<NB_AGG, 256>>>(x);
    gemm_mma<0><<<NB_GEMM, 256>>>(agg, x, W1l, W1r, b1, h1);
    // Layer 2
    k_aggregate<<<NB_AGG, 256>>>(h1);
    gemm_mma<0><<<NB_GEMM, 256>>>(agg, h1, W2l, W2r, b2, h2);
    // Layer 3 (post-aggregation by linearity): PR = h2 @ [W3l | W3r] (+b3 on R)
    gemm_mma<1><<<NB_GEMM, 256>>>(h2, h2, W3l, W3r, b3, agg);
    k_agg_add<<<NB_AGG, 256>>>(agg, out);
}